// round 7
// baseline (speedup 1.0000x reference)
#include <cuda_runtime.h>
#include <cuda_fp16.h>
#include <math.h>

#define H_    4096
#define NH_   32
#define NKV_  8
#define HD_   128
#define S_    2048
#define B_    2
#define SCALE_ 0.08838834764831845f   // 128^-0.5

// ---------------- scratch (device globals; no allocations allowed) ----------
__device__ float    g_qlin[(size_t)B_ * S_ * H_];
__device__ float    g_kvlin[(size_t)B_ * S_ * 2 * NKV_ * HD_];   // fused K|V
__device__ float    g_q[(size_t)B_ * NH_ * S_ * HD_];
__device__ float    g_k[(size_t)B_ * NKV_ * S_ * HD_];
__device__ float    g_v[(size_t)B_ * NKV_ * S_ * HD_];
__device__ __half   g_hs_h[(size_t)B_ * S_ * H_];
__device__ __half   g_wq_h[(size_t)H_ * H_];
__device__ __half   g_wkv_h[(size_t)2 * NKV_ * HD_ * H_];        // stacked Wk|Wv
__device__ __half   g_wo_h[(size_t)H_ * H_];
__device__ __half   g_att_h[(size_t)B_ * S_ * H_];
__device__ float    g_bkv[2 * NKV_ * HD_];                       // bk|bv

// ---------------- helpers ----------------------------------------------------
__device__ __forceinline__ unsigned f2tf32(float f) {
    unsigned r;
    asm("cvt.rna.tf32.f32 %0, %1;" : "=r"(r) : "f"(f));
    return r;
}

__device__ __forceinline__ void mma_tf32(float c[4], const unsigned a[4], const unsigned b[2]) {
    asm volatile(
        "mma.sync.aligned.m16n8k8.row.col.f32.tf32.tf32.f32 "
        "{%0,%1,%2,%3}, {%4,%5,%6,%7}, {%8,%9}, {%0,%1,%2,%3};\n"
        : "+f"(c[0]), "+f"(c[1]), "+f"(c[2]), "+f"(c[3])
        : "r"(a[0]), "r"(a[1]), "r"(a[2]), "r"(a[3]), "r"(b[0]), "r"(b[1]));
}

__device__ __forceinline__ void mma_f16(float c[4], const unsigned a[4],
                                        unsigned b0, unsigned b1) {
    asm volatile(
        "mma.sync.aligned.m16n8k16.row.col.f32.f16.f16.f32 "
        "{%0,%1,%2,%3}, {%4,%5,%6,%7}, {%8,%9}, {%0,%1,%2,%3};\n"
        : "+f"(c[0]), "+f"(c[1]), "+f"(c[2]), "+f"(c[3])
        : "r"(a[0]), "r"(a[1]), "r"(a[2]), "r"(a[3]), "r"(b0), "r"(b1));
}

__device__ __forceinline__ void ldsm_x4(unsigned r[4], unsigned addr) {
    asm volatile("ldmatrix.sync.aligned.m8n8.x4.shared.b16 {%0,%1,%2,%3}, [%4];"
                 : "=r"(r[0]), "=r"(r[1]), "=r"(r[2]), "=r"(r[3]) : "r"(addr));
}

__device__ __forceinline__ unsigned smem_u32(const void* p) {
    return (unsigned)__cvta_generic_to_shared(p);
}

// ---------------- convert fp32 -> fp16 ---------------------------------------
__global__ __launch_bounds__(256) void cvt_f16_kernel(
    const float4* __restrict__ in, uint2* __restrict__ out, int n4)
{
    int i = blockIdx.x * blockDim.x + threadIdx.x;
    if (i < n4) {
        float4 v = in[i];
        __half2 h0 = __floats2half2_rn(v.x, v.y);
        __half2 h1 = __floats2half2_rn(v.z, v.w);
        uint2 u;
        u.x = *(unsigned*)&h0;
        u.y = *(unsigned*)&h1;
        out[i] = u;
    }
}

__global__ void bias_cat_kernel(const float* __restrict__ a,
                                const float* __restrict__ b,
                                float* __restrict__ o)
{
    int i = blockIdx.x * blockDim.x + threadIdx.x;
    int n = NKV_ * HD_;
    if (i < n) o[i] = a[i];
    else if (i < 2 * n) o[i] = b[i - n];
}

// ---------------- pipelined fp16 GEMM (ldmatrix): C = A @ B^T (+bias) --------
// 128x128x64 tiles, cp.async 2-stage, 8 warps (2m x 4n), warp 64x32.
#define GSTH 36                       // smem row stride (32-bit words); 36%32==4
#define GSTAGE_H (128 * GSTH)         // words per operand per stage
#define GSTAGE_BYTES (2 * GSTAGE_H * 4)
#define GEMM_SMEM_H (2 * GSTAGE_BYTES)   // 73728 bytes

__global__ __launch_bounds__(256, 2) void gemm_f16p(
    const __half* __restrict__ A, const __half* __restrict__ Bm,
    const float* __restrict__ bias, float* __restrict__ C,
    int M, int N, int K)
{
    extern __shared__ unsigned sh[];

    int tid = threadIdx.x;
    int warp = tid >> 5, lane = tid & 31;
    int r = lane >> 2, cq = lane & 3;
    int wm = (warp >> 2) * 64, wn = (warp & 3) * 32;
    int bm = blockIdx.y * 128, bn = blockIdx.x * 128;
    int Kw = K >> 1;                  // K in 32-bit words (half2)

    float acc[4][4][4];
#pragma unroll
    for (int mi = 0; mi < 4; mi++)
#pragma unroll
        for (int ni = 0; ni < 4; ni++)
#pragma unroll
            for (int t = 0; t < 4; t++) acc[mi][ni][t] = 0.f;

    // ldmatrix addresses (stage 0, kstep 0), byte units
    unsigned sbase = smem_u32(sh);
    int sub = lane >> 3, l7 = lane & 7;
    unsigned aaddr[4], baddr[2];
#pragma unroll
    for (int mi = 0; mi < 4; mi++) {
        int row = wm + mi * 16 + (sub & 1) * 8 + l7;
        int wcol = (sub >> 1) * 4;
        aaddr[mi] = sbase + (row * GSTH + wcol) * 4;
    }
#pragma unroll
    for (int p = 0; p < 2; p++) {
        int row = wn + p * 16 + (sub >> 1) * 8 + l7;
        int wcol = (sub & 1) * 4;
        baddr[p] = sbase + (GSTAGE_H + row * GSTH + wcol) * 4;
    }

    // cp.async: tile = 128 rows x 32 words, 1024 quads, 4/thread per operand
    int qrow = tid >> 3, qq = (tid & 7) << 2;

    const unsigned* Ab = (const unsigned*)A + (size_t)bm * Kw;
    const unsigned* Bb = (const unsigned*)Bm + (size_t)bn * Kw;

    auto load_stage = [&](int kt, int s) {
        unsigned* As = sh + s * 2 * GSTAGE_H;
        unsigned* Bs = As + GSTAGE_H;
        int k0 = kt << 5;
#pragma unroll
        for (int i = 0; i < 4; i++) {
            int row = qrow + i * 32;
            unsigned da = smem_u32(&As[row * GSTH + qq]);
            const unsigned* sa = Ab + (size_t)row * Kw + k0 + qq;
            asm volatile("cp.async.cg.shared.global [%0], [%1], 16;\n" :: "r"(da), "l"(sa));
            unsigned db = smem_u32(&Bs[row * GSTH + qq]);
            const unsigned* sb = Bb + (size_t)row * Kw + k0 + qq;
            asm volatile("cp.async.cg.shared.global [%0], [%1], 16;\n" :: "r"(db), "l"(sb));
        }
        asm volatile("cp.async.commit_group;\n");
    };

    int nt = K >> 6;
    load_stage(0, 0);

    for (int kt = 0; kt < nt; kt++) {
        if (kt + 1 < nt) {
            load_stage(kt + 1, (kt + 1) & 1);
            asm volatile("cp.async.wait_group 1;\n");
        } else {
            asm volatile("cp.async.wait_group 0;\n");
        }
        __syncthreads();

        unsigned so = (kt & 1) * GSTAGE_BYTES;
#pragma unroll
        for (int k = 0; k < 32; k += 8) {     // 4 k16 steps
            unsigned a[4][4], bfr[2][4];
#pragma unroll
            for (int mi = 0; mi < 4; mi++)
                ldsm_x4(a[mi], aaddr[mi] + so + k * 4);
#pragma unroll
            for (int p = 0; p < 2; p++)
                ldsm_x4(bfr[p], baddr[p] + so + k * 4);
#pragma unroll
            for (int mi = 0; mi < 4; mi++)
#pragma unroll
                for (int ni = 0; ni < 4; ni++)
                    mma_f16(acc[mi][ni], a[mi],
                            bfr[ni >> 1][(ni & 1) * 2], bfr[ni >> 1][(ni & 1) * 2 + 1]);
        }
        __syncthreads();
    }

#pragma unroll
    for (int mi = 0; mi < 4; mi++) {
#pragma unroll
        for (int ni = 0; ni < 4; ni++) {
            int row = bm + wm + mi * 16 + r;
            int col = bn + wn + ni * 8 + cq * 2;
            float b0 = 0.f, b1 = 0.f;
            if (bias) { b0 = bias[col]; b1 = bias[col + 1]; }
            float2 v0, v1;
            v0.x = acc[mi][ni][0] + b0; v0.y = acc[mi][ni][1] + b1;
            v1.x = acc[mi][ni][2] + b0; v1.y = acc[mi][ni][3] + b1;
            *(float2*)(C + (size_t)row * N + col) = v0;
            *(float2*)(C + (size_t)(row + 8) * N + col) = v1;
        }
    }
}

// ---------------- RoPE + head transpose --------------------------------------
// reads [B,S,rowstride] at coloff, writes [B,nh,S,HD]
__global__ void rope_kernel(const float* __restrict__ X, const float* __restrict__ cs,
                            const float* __restrict__ sn, float* __restrict__ out,
                            int nheads, int rowstride, int coloff)
{
    int idx = blockIdx.x * blockDim.x + threadIdx.x;
    int d  = idx & (HD_ - 1);
    int s  = (idx >> 7) & (S_ - 1);
    int bh = idx >> 18;
    int h  = bh % nheads;
    int b  = bh / nheads;
    const float* xp = X + (size_t)(b * S_ + s) * rowstride + coloff + h * HD_;
    int dd = d & 63;
    float c = cs[s * 64 + dd], si = sn[s * 64 + dd];
    float x1 = xp[2 * dd], x2 = xp[2 * dd + 1];
    out[idx] = (d < 64) ? (x1 * c - x2 * si) : (x1 * si + x2 * c);
}

__global__ void vtrans_kernel(const float* __restrict__ X, float* __restrict__ out,
                              int rowstride, int coloff)
{
    int idx = blockIdx.x * blockDim.x + threadIdx.x;
    int d  = idx & (HD_ - 1);
    int s  = (idx >> 7) & (S_ - 1);
    int bh = idx >> 18;
    int h  = bh % NKV_;
    int b  = bh / NKV_;
    out[idx] = X[(size_t)(b * S_ + s) * rowstride + coloff + h * HD_ + d];
}

// ---------------- Tensor-core flash attention (tf32) -> fp16 out -------------
#define AQ  128
#define AKV 64
#define QKS 132
#define VSS 136
#define PSS 68

#define QS_OFF 0
#define KS_OFF (AQ * QKS)
#define VS_OFF (KS_OFF + AKV * QKS)
#define PS_OFF (VS_OFF + AKV * VSS)
#define ATT_WORDS (PS_OFF + AQ * PSS)
#define ATT_SMEM (ATT_WORDS * 4)

__global__ __launch_bounds__(256) void attn_tc_kernel(
    const float* __restrict__ Q,  // [B,NH,S,HD]
    const float* __restrict__ K,  // [B,NKV,S,HD]
    const float* __restrict__ V,  // [B,NKV,S,HD]
    __half* __restrict__ O)       // [B,S,NH,HD] fp16
{
    extern __shared__ unsigned smw[];
    unsigned* Qs = smw + QS_OFF;
    unsigned* Ks = smw + KS_OFF;
    unsigned* Vs = smw + VS_OFF;
    unsigned* Ps = smw + PS_OFF;

    int tid = threadIdx.x;
    int warp = tid >> 5, lane = tid & 31;
    int r = lane >> 2, cq = lane & 3;
    int m0 = warp * 16;

    int qt = blockIdx.x, h = blockIdx.y, b = blockIdx.z;
    int kvh = h >> 2;
    const float* Qp = Q + (((size_t)b * NH_ + h) * S_ + qt * AQ) * HD_;
    const float* Kp = K + ((size_t)b * NKV_ + kvh) * S_ * HD_;
    const float* Vp = V + ((size_t)b * NKV_ + kvh) * S_ * HD_;

#pragma unroll
    for (int i = 0; i < 16; i++) {
        int fidx = tid + i * 256;
        int rr = fidx >> 5, c4 = (fidx & 31) << 2;
        float4 v = *(const float4*)(Qp + (size_t)rr * HD_ + c4);
        uint4 u;
        u.x = f2tf32(v.x * SCALE_); u.y = f2tf32(v.y * SCALE_);
        u.z = f2tf32(v.z * SCALE_); u.w = f2tf32(v.w * SCALE_);
        *(uint4*)&Qs[rr * QKS + c4] = u;
    }

    float mx0 = -1e30f, mx8 = -1e30f, l0 = 0.f, l8 = 0.f;
    float oa[16][4];
#pragma unroll
    for (int j = 0; j < 16; j++)
#pragma unroll
        for (int t = 0; t < 4; t++) oa[j][t] = 0.f;

    for (int kt = 0; kt < S_ / AKV; kt++) {
        __syncthreads();
        const float* Kt = Kp + (size_t)kt * AKV * HD_;
        const float* Vt = Vp + (size_t)kt * AKV * HD_;
#pragma unroll
        for (int i = 0; i < 8; i++) {
            int fidx = tid + i * 256;
            int rr = fidx >> 5, c4 = (fidx & 31) << 2;
            float4 kv4 = *(const float4*)(Kt + (size_t)rr * HD_ + c4);
            uint4 ku;
            ku.x = f2tf32(kv4.x); ku.y = f2tf32(kv4.y);
            ku.z = f2tf32(kv4.z); ku.w = f2tf32(kv4.w);
            *(uint4*)&Ks[rr * QKS + c4] = ku;
            float4 vv4 = *(const float4*)(Vt + (size_t)rr * HD_ + c4);
            uint4 vu;
            vu.x = f2tf32(vv4.x); vu.y = f2tf32(vv4.y);
            vu.z = f2tf32(vv4.z); vu.w = f2tf32(vv4.w);
            *(uint4*)&Vs[rr * VSS + c4] = vu;
        }
        __syncthreads();

        float sc[8][4];
#pragma unroll
        for (int j = 0; j < 8; j++)
#pragma unroll
            for (int t = 0; t < 4; t++) sc[j][t] = 0.f;

#pragma unroll
        for (int k8 = 0; k8 < 16; k8++) {
            int k = k8 * 8;
            unsigned a[4];
            int abase = (m0 + r) * QKS + k + cq;
            a[0] = Qs[abase];
            a[1] = Qs[abase + 8 * QKS];
            a[2] = Qs[abase + 4];
            a[3] = Qs[abase + 8 * QKS + 4];
#pragma unroll
            for (int j = 0; j < 8; j++) {
                unsigned bfr[2];
                int bbase = (j * 8 + r) * QKS + k + cq;
                bfr[0] = Ks[bbase];
                bfr[1] = Ks[bbase + 4];
                mma_tf32(sc[j], a, bfr);
            }
        }

        float tm0 = -1e30f, tm8 = -1e30f;
#pragma unroll
        for (int j = 0; j < 8; j++) {
            tm0 = fmaxf(tm0, fmaxf(sc[j][0], sc[j][1]));
            tm8 = fmaxf(tm8, fmaxf(sc[j][2], sc[j][3]));
        }
        tm0 = fmaxf(tm0, __shfl_xor_sync(0xffffffffu, tm0, 1));
        tm0 = fmaxf(tm0, __shfl_xor_sync(0xffffffffu, tm0, 2));
        tm8 = fmaxf(tm8, __shfl_xor_sync(0xffffffffu, tm8, 1));
        tm8 = fmaxf(tm8, __shfl_xor_sync(0xffffffffu, tm8, 2));

        float nm0 = fmaxf(mx0, tm0), nm8 = fmaxf(mx8, tm8);
        float cr0 = __expf(mx0 - nm0), cr8 = __expf(mx8 - nm8);
        mx0 = nm0; mx8 = nm8;

        float rs0 = 0.f, rs8 = 0.f;
#pragma unroll
        for (int j = 0; j < 8; j++) {
            float p0 = __expf(sc[j][0] - nm0);
            float p1 = __expf(sc[j][1] - nm0);
            float p2 = __expf(sc[j][2] - nm8);
            float p3 = __expf(sc[j][3] - nm8);
            rs0 += p0 + p1; rs8 += p2 + p3;
            int col = j * 8 + cq * 2;
            Ps[(m0 + r) * PSS + col]     = f2tf32(p0);
            Ps[(m0 + r) * PSS + col + 1] = f2tf32(p1);
            Ps[(m0 + r + 8) * PSS + col]     = f2tf32(p2);
            Ps[(m0 + r + 8) * PSS + col + 1] = f2tf32(p3);
        }
        rs0 += __shfl_xor_sync(0xffffffffu, rs0, 1);
        rs0 += __shfl_xor_sync(0xffffffffu, rs0, 2);
        rs8 += __shfl_xor_sync(0xffffffffu, rs8, 1);
        rs8 += __shfl_xor_sync(0xffffffffu, rs8, 2);
        l0 = l0 * cr0 + rs0;
        l8 = l8 * cr8 + rs8;

#pragma unroll
        for (int j = 0; j < 16; j++) {
            oa[j][0] *= cr0; oa[j][1] *= cr0;
            oa[j][2] *= cr8; oa[j][3] *= cr8;
        }
        __syncwarp();

#pragma unroll
        for (int kk8 = 0; kk8 < 8; kk8++) {
            int kk = kk8 * 8;
            unsigned a[4];
            int abase = (m0 + r) * PSS + kk + cq;
            a[0] = Ps[abase];
            a[1] = Ps[abase + 8 * PSS];
            a[2] = Ps[abase + 4];
            a[3] = Ps[abase + 8 * PSS + 4];
#pragma unroll
            for (int j = 0; j < 16; j++) {
                unsigned bfr[2];
                bfr[0] = Vs[(kk + cq) * VSS + j * 8 + r];
                bfr[1] = Vs[(kk + cq + 4) * VSS + j * 8 + r];
                mma_tf32(oa[j], a, bfr);
            }
        }
    }

    float inv0 = 1.f / l0, inv8 = 1.f / l8;
    int row0g = qt * AQ + m0 + r;
    int row8g = row0g + 8;
#pragma unroll
    for (int j = 0; j < 16; j++) {
        int col = j * 8 + cq * 2;
        __half2 h0 = __floats2half2_rn(oa[j][0] * inv0, oa[j][1] * inv0);
        __half2 h1 = __floats2half2_rn(oa[j][2] * inv8, oa[j][3] * inv8);
        *(__half2*)(O + (((size_t)b * S_ + row0g) * NH_ + h) * HD_ + col) = h0;
        *(__half2*)(O + (((size_t)b * S_ + row8g) * NH_ + h) * HD_ + col) = h1;
    }
}

// ---------------- launcher ----------------------------------------------------
extern "C" void kernel_launch(void* const* d_in, const int* in_sizes, int n_in,
                              void* d_out, int out_size)
{
    const float* hs   = (const float*)d_in[0];
    const float* cosb = (const float*)d_in[1];
    const float* sinb = (const float*)d_in[2];
    const float* Wq   = (const float*)d_in[3];
    const float* Wk   = (const float*)d_in[4];
    const float* bk   = (const float*)d_in[5];
    const float* Wv   = (const float*)d_in[6];
    const float* bv   = (const float*)d_in[7];
    const float* Wo   = (const float*)d_in[8];
    float* out = (float*)d_out;

    float *qlin, *kvlin, *q, *k, *v, *bkv;
    __half *hs_h, *wq_h, *wkv_h, *wo_h, *att_h;
    cudaGetSymbolAddress((void**)&qlin,  g_qlin);
    cudaGetSymbolAddress((void**)&kvlin, g_kvlin);
    cudaGetSymbolAddress((void**)&q,     g_q);
    cudaGetSymbolAddress((void**)&k,     g_k);
    cudaGetSymbolAddress((void**)&v,     g_v);
    cudaGetSymbolAddress((void**)&hs_h,  g_hs_h);
    cudaGetSymbolAddress((void**)&wq_h,  g_wq_h);
    cudaGetSymbolAddress((void**)&wkv_h, g_wkv_h);
    cudaGetSymbolAddress((void**)&wo_h,  g_wo_h);
    cudaGetSymbolAddress((void**)&att_h, g_att_h);
    cudaGetSymbolAddress((void**)&bkv,   g_bkv);

    const int M = B_ * S_;           // 4096
    const int NKVD = NKV_ * HD_;     // 1024

    // convert operands to fp16 (+ stack Wk|Wv, concat biases)
    int n4a = (M * H_) / 4;
    int n4b = (NKVD * H_) / 4;
    cvt_f16_kernel<<<n4a / 256, 256>>>((const float4*)hs, (uint2*)hs_h, n4a);
    cvt_f16_kernel<<<n4a / 256, 256>>>((const float4*)Wq, (uint2*)wq_h, n4a);
    cvt_f16_kernel<<<n4b / 256, 256>>>((const float4*)Wk, (uint2*)wkv_h, n4b);
    cvt_f16_kernel<<<n4b / 256, 256>>>((const float4*)Wv,
                                       (uint2*)wkv_h + (size_t)NKVD * H_ / 4, n4b);
    cvt_f16_kernel<<<n4a / 256, 256>>>((const float4*)Wo, (uint2*)wo_h, n4a);
    bias_cat_kernel<<<(2 * NKVD) / 256, 256>>>(bk, bv, bkv);

    // projections (fp16 ldmatrix GEMMs, fp32 accumulate)
    cudaFuncSetAttribute(gemm_f16p, cudaFuncAttributeMaxDynamicSharedMemorySize, GEMM_SMEM_H);
    gemm_f16p<<<dim3(H_ / 128, M / 128), 256, GEMM_SMEM_H>>>(hs_h, wq_h, nullptr, qlin, M, H_, H_);
    gemm_f16p<<<dim3((2 * NKVD) / 128, M / 128), 256, GEMM_SMEM_H>>>(hs_h, wkv_h, bkv, kvlin, M, 2 * NKVD, H_);

    // rope + layout
    rope_kernel<<<(B_ * NH_ * S_ * HD_) / 256, 256>>>(qlin, cosb, sinb, q, NH_, H_, 0);
    rope_kernel<<<(B_ * NKV_ * S_ * HD_) / 256, 256>>>(kvlin, cosb, sinb, k, NKV_, 2 * NKVD, 0);
    vtrans_kernel<<<(B_ * NKV_ * S_ * HD_) / 256, 256>>>(kvlin, v, 2 * NKVD, NKVD);

    // attention (tf32 tensor-core) -> fp16 output
    cudaFuncSetAttribute(attn_tc_kernel, cudaFuncAttributeMaxDynamicSharedMemorySize, ATT_SMEM);
    attn_tc_kernel<<<dim3(S_ / AQ, NH_, B_), 256, ATT_SMEM>>>(q, k, v, att_h);

    // output projection
    gemm_f16p<<<dim3(H_ / 128, M / 128), 256, GEMM_SMEM_H>>>(att_h, wo_h, nullptr, out, M, H_, H_);
}

// round 8
// speedup vs baseline: 1.3973x; 1.3973x over previous
#include <cuda_runtime.h>
#include <cuda_fp16.h>
#include <math.h>

#define H_    4096
#define NH_   32
#define NKV_  8
#define HD_   128
#define S_    2048
#define B_    2
#define SCALE_ 0.08838834764831845f   // 128^-0.5

// ---------------- scratch (device globals; no allocations allowed) ----------
__device__ float    g_qlin[(size_t)B_ * S_ * H_];
__device__ float    g_kvlin[(size_t)B_ * S_ * 2 * NKV_ * HD_];   // fused K|V
__device__ float    g_q[(size_t)B_ * NH_ * S_ * HD_];
__device__ float    g_k[(size_t)B_ * NKV_ * S_ * HD_];
__device__ float    g_v[(size_t)B_ * NKV_ * S_ * HD_];
__device__ __half   g_hs_h[(size_t)B_ * S_ * H_];
__device__ __half   g_wq_h[(size_t)H_ * H_];
__device__ __half   g_wkv_h[(size_t)2 * NKV_ * HD_ * H_];        // stacked Wk|Wv
__device__ __half   g_wo_h[(size_t)H_ * H_];
__device__ __half   g_att_h[(size_t)B_ * S_ * H_];
__device__ float    g_bkv[2 * NKV_ * HD_];                       // bk|bv

// ---------------- helpers ----------------------------------------------------
__device__ __forceinline__ unsigned f2tf32(float f) {
    unsigned r;
    asm("cvt.rna.tf32.f32 %0, %1;" : "=r"(r) : "f"(f));
    return r;
}

__device__ __forceinline__ void mma_tf32(float c[4], const unsigned a[4], const unsigned b[2]) {
    asm volatile(
        "mma.sync.aligned.m16n8k8.row.col.f32.tf32.tf32.f32 "
        "{%0,%1,%2,%3}, {%4,%5,%6,%7}, {%8,%9}, {%0,%1,%2,%3};\n"
        : "+f"(c[0]), "+f"(c[1]), "+f"(c[2]), "+f"(c[3])
        : "r"(a[0]), "r"(a[1]), "r"(a[2]), "r"(a[3]), "r"(b[0]), "r"(b[1]));
}

__device__ __forceinline__ void mma_f16(float c[4], const unsigned a[4], const unsigned b[2]) {
    asm volatile(
        "mma.sync.aligned.m16n8k16.row.col.f32.f16.f16.f32 "
        "{%0,%1,%2,%3}, {%4,%5,%6,%7}, {%8,%9}, {%0,%1,%2,%3};\n"
        : "+f"(c[0]), "+f"(c[1]), "+f"(c[2]), "+f"(c[3])
        : "r"(a[0]), "r"(a[1]), "r"(a[2]), "r"(a[3]), "r"(b[0]), "r"(b[1]));
}

__device__ __forceinline__ unsigned smem_u32(const void* p) {
    return (unsigned)__cvta_generic_to_shared(p);
}

// ---------------- convert fp32 -> fp16 ---------------------------------------
__global__ __launch_bounds__(256) void cvt_f16_kernel(
    const float4* __restrict__ in, uint2* __restrict__ out, int n4)
{
    int i = blockIdx.x * blockDim.x + threadIdx.x;
    if (i < n4) {
        float4 v = in[i];
        __half2 h0 = __floats2half2_rn(v.x, v.y);
        __half2 h1 = __floats2half2_rn(v.z, v.w);
        uint2 u;
        u.x = *(unsigned*)&h0;
        u.y = *(unsigned*)&h1;
        out[i] = u;
    }
}

__global__ void bias_cat_kernel(const float* __restrict__ a,
                                const float* __restrict__ b,
                                float* __restrict__ o)
{
    int i = blockIdx.x * blockDim.x + threadIdx.x;
    int n = NKV_ * HD_;
    if (i < n) o[i] = a[i];
    else if (i < 2 * n) o[i] = b[i - n];
}

// ---------------- pipelined fp16 GEMM: C = A @ B^T (+bias), f32 accum --------
// 128x128x64 tiles, cp.async 3-stage, 8 warps (2m x 4n), warp 64x32.
#define GSTH 36                       // smem row stride (32-bit words); 36%32==4
#define GSTAGE_H (128 * GSTH)         // words per operand per stage
#define NSTAGE 3
#define GEMM_SMEM_H (NSTAGE * 2 * GSTAGE_H * 4)   // 110592 bytes

__global__ __launch_bounds__(256, 2) void gemm_f16p(
    const __half* __restrict__ A, const __half* __restrict__ Bm,
    const float* __restrict__ bias, float* __restrict__ C,
    int M, int N, int K)
{
    extern __shared__ unsigned sh[];

    int tid = threadIdx.x;
    int warp = tid >> 5, lane = tid & 31;
    int r = lane >> 2, cq = lane & 3;
    int wm = (warp >> 2) * 64, wn = (warp & 3) * 32;
    int bm = blockIdx.y * 128, bn = blockIdx.x * 128;
    int Kw = K >> 1;                  // K in 32-bit words (half2)

    float acc[4][4][4];
#pragma unroll
    for (int mi = 0; mi < 4; mi++)
#pragma unroll
        for (int ni = 0; ni < 4; ni++)
#pragma unroll
            for (int t = 0; t < 4; t++) acc[mi][ni][t] = 0.f;

    // cp.async: tile = 128 rows x 32 words = 8 quads/row, 1024 quads, 4/thread
    int qrow = tid >> 3, qq = (tid & 7) << 2;

    const unsigned* Ab = (const unsigned*)A + (size_t)bm * Kw;
    const unsigned* Bb = (const unsigned*)Bm + (size_t)bn * Kw;

    auto load_stage = [&](int kt, int s) {
        unsigned* As = sh + s * 2 * GSTAGE_H;
        unsigned* Bs = As + GSTAGE_H;
        int k0 = kt << 5;             // word offset
#pragma unroll
        for (int i = 0; i < 4; i++) {
            int row = qrow + i * 32;
            unsigned da = smem_u32(&As[row * GSTH + qq]);
            const unsigned* sa = Ab + (size_t)row * Kw + k0 + qq;
            asm volatile("cp.async.cg.shared.global [%0], [%1], 16;\n" :: "r"(da), "l"(sa));
            unsigned db = smem_u32(&Bs[row * GSTH + qq]);
            const unsigned* sb = Bb + (size_t)row * Kw + k0 + qq;
            asm volatile("cp.async.cg.shared.global [%0], [%1], 16;\n" :: "r"(db), "l"(sb));
        }
        asm volatile("cp.async.commit_group;\n");
    };

    int nt = K >> 6;                  // 64 halves (32 words) per tile
    load_stage(0, 0);
    if (nt > 1) load_stage(1, 1);

    for (int kt = 0; kt < nt; kt++) {
        if (kt + 2 < nt) {
            load_stage(kt + 2, (kt + 2) % NSTAGE);
            asm volatile("cp.async.wait_group 2;\n");
        } else if (kt + 1 < nt) {
            asm volatile("cp.async.wait_group 1;\n");
        } else {
            asm volatile("cp.async.wait_group 0;\n");
        }
        __syncthreads();

        unsigned* As = sh + (kt % NSTAGE) * 2 * GSTAGE_H;
        unsigned* Bs = As + GSTAGE_H;
#pragma unroll
        for (int k = 0; k < 32; k += 8) {     // 4 k16 steps
            unsigned a[4][4], b[4][2];
#pragma unroll
            for (int mi = 0; mi < 4; mi++) {
                int base = (wm + mi * 16 + r) * GSTH + k + cq;
                a[mi][0] = As[base];
                a[mi][1] = As[base + 8 * GSTH];
                a[mi][2] = As[base + 4];
                a[mi][3] = As[base + 8 * GSTH + 4];
            }
#pragma unroll
            for (int ni = 0; ni < 4; ni++) {
                int base = (wn + ni * 8 + r) * GSTH + k + cq;
                b[ni][0] = Bs[base];
                b[ni][1] = Bs[base + 4];
            }
#pragma unroll
            for (int mi = 0; mi < 4; mi++)
#pragma unroll
                for (int ni = 0; ni < 4; ni++)
                    mma_f16(acc[mi][ni], a[mi], b[ni]);
        }
        __syncthreads();
    }

#pragma unroll
    for (int mi = 0; mi < 4; mi++) {
#pragma unroll
        for (int ni = 0; ni < 4; ni++) {
            int row = bm + wm + mi * 16 + r;
            int col = bn + wn + ni * 8 + cq * 2;
            float b0 = 0.f, b1 = 0.f;
            if (bias) { b0 = bias[col]; b1 = bias[col + 1]; }
            float2 v0, v1;
            v0.x = acc[mi][ni][0] + b0; v0.y = acc[mi][ni][1] + b1;
            v1.x = acc[mi][ni][2] + b0; v1.y = acc[mi][ni][3] + b1;
            *(float2*)(C + (size_t)row * N + col) = v0;
            *(float2*)(C + (size_t)(row + 8) * N + col) = v1;
        }
    }
}

// ---------------- RoPE + head transpose --------------------------------------
// reads [B,S,rowstride] at coloff, writes [B,nh,S,HD]
__global__ void rope_kernel(const float* __restrict__ X, const float* __restrict__ cs,
                            const float* __restrict__ sn, float* __restrict__ out,
                            int nheads, int rowstride, int coloff)
{
    int idx = blockIdx.x * blockDim.x + threadIdx.x;
    int d  = idx & (HD_ - 1);
    int s  = (idx >> 7) & (S_ - 1);
    int bh = idx >> 18;
    int h  = bh % nheads;
    int b  = bh / nheads;
    const float* xp = X + (size_t)(b * S_ + s) * rowstride + coloff + h * HD_;
    int dd = d & 63;
    float c = cs[s * 64 + dd], si = sn[s * 64 + dd];
    float x1 = xp[2 * dd], x2 = xp[2 * dd + 1];
    out[idx] = (d < 64) ? (x1 * c - x2 * si) : (x1 * si + x2 * c);
}

__global__ void vtrans_kernel(const float* __restrict__ X, float* __restrict__ out,
                              int rowstride, int coloff)
{
    int idx = blockIdx.x * blockDim.x + threadIdx.x;
    int d  = idx & (HD_ - 1);
    int s  = (idx >> 7) & (S_ - 1);
    int bh = idx >> 18;
    int h  = bh % NKV_;
    int b  = bh / NKV_;
    out[idx] = X[(size_t)(b * S_ + s) * rowstride + coloff + h * HD_ + d];
}

// ---------------- Tensor-core flash attention (tf32) -> fp16 out -------------
#define AQ  128
#define AKV 64
#define QKS 132
#define VSS 136
#define PSS 68

#define QS_OFF 0
#define KS_OFF (AQ * QKS)
#define VS_OFF (KS_OFF + AKV * QKS)
#define PS_OFF (VS_OFF + AKV * VSS)
#define ATT_WORDS (PS_OFF + AQ * PSS)
#define ATT_SMEM (ATT_WORDS * 4)

__global__ __launch_bounds__(256) void attn_tc_kernel(
    const float* __restrict__ Q,  // [B,NH,S,HD]
    const float* __restrict__ K,  // [B,NKV,S,HD]
    const float* __restrict__ V,  // [B,NKV,S,HD]
    __half* __restrict__ O)       // [B,S,NH,HD] fp16
{
    extern __shared__ unsigned smw[];
    unsigned* Qs = smw + QS_OFF;
    unsigned* Ks = smw + KS_OFF;
    unsigned* Vs = smw + VS_OFF;
    unsigned* Ps = smw + PS_OFF;

    int tid = threadIdx.x;
    int warp = tid >> 5, lane = tid & 31;
    int r = lane >> 2, cq = lane & 3;
    int m0 = warp * 16;

    int qt = blockIdx.x, h = blockIdx.y, b = blockIdx.z;
    int kvh = h >> 2;
    const float* Qp = Q + (((size_t)b * NH_ + h) * S_ + qt * AQ) * HD_;
    const float* Kp = K + ((size_t)b * NKV_ + kvh) * S_ * HD_;
    const float* Vp = V + ((size_t)b * NKV_ + kvh) * S_ * HD_;

#pragma unroll
    for (int i = 0; i < 16; i++) {
        int fidx = tid + i * 256;
        int rr = fidx >> 5, c4 = (fidx & 31) << 2;
        float4 v = *(const float4*)(Qp + (size_t)rr * HD_ + c4);
        uint4 u;
        u.x = f2tf32(v.x * SCALE_); u.y = f2tf32(v.y * SCALE_);
        u.z = f2tf32(v.z * SCALE_); u.w = f2tf32(v.w * SCALE_);
        *(uint4*)&Qs[rr * QKS + c4] = u;
    }

    float mx0 = -1e30f, mx8 = -1e30f, l0 = 0.f, l8 = 0.f;
    float oa[16][4];
#pragma unroll
    for (int j = 0; j < 16; j++)
#pragma unroll
        for (int t = 0; t < 4; t++) oa[j][t] = 0.f;

    for (int kt = 0; kt < S_ / AKV; kt++) {
        __syncthreads();
        const float* Kt = Kp + (size_t)kt * AKV * HD_;
        const float* Vt = Vp + (size_t)kt * AKV * HD_;
#pragma unroll
        for (int i = 0; i < 8; i++) {
            int fidx = tid + i * 256;
            int rr = fidx >> 5, c4 = (fidx & 31) << 2;
            float4 kv4 = *(const float4*)(Kt + (size_t)rr * HD_ + c4);
            uint4 ku;
            ku.x = f2tf32(kv4.x); ku.y = f2tf32(kv4.y);
            ku.z = f2tf32(kv4.z); ku.w = f2tf32(kv4.w);
            *(uint4*)&Ks[rr * QKS + c4] = ku;
            float4 vv4 = *(const float4*)(Vt + (size_t)rr * HD_ + c4);
            uint4 vu;
            vu.x = f2tf32(vv4.x); vu.y = f2tf32(vv4.y);
            vu.z = f2tf32(vv4.z); vu.w = f2tf32(vv4.w);
            *(uint4*)&Vs[rr * VSS + c4] = vu;
        }
        __syncthreads();

        float sc[8][4];
#pragma unroll
        for (int j = 0; j < 8; j++)
#pragma unroll
            for (int t = 0; t < 4; t++) sc[j][t] = 0.f;

#pragma unroll
        for (int k8 = 0; k8 < 16; k8++) {
            int k = k8 * 8;
            unsigned a[4];
            int abase = (m0 + r) * QKS + k + cq;
            a[0] = Qs[abase];
            a[1] = Qs[abase + 8 * QKS];
            a[2] = Qs[abase + 4];
            a[3] = Qs[abase + 8 * QKS + 4];
#pragma unroll
            for (int j = 0; j < 8; j++) {
                unsigned bfr[2];
                int bbase = (j * 8 + r) * QKS + k + cq;
                bfr[0] = Ks[bbase];
                bfr[1] = Ks[bbase + 4];
                mma_tf32(sc[j], a, bfr);
            }
        }

        float tm0 = -1e30f, tm8 = -1e30f;
#pragma unroll
        for (int j = 0; j < 8; j++) {
            tm0 = fmaxf(tm0, fmaxf(sc[j][0], sc[j][1]));
            tm8 = fmaxf(tm8, fmaxf(sc[j][2], sc[j][3]));
        }
        tm0 = fmaxf(tm0, __shfl_xor_sync(0xffffffffu, tm0, 1));
        tm0 = fmaxf(tm0, __shfl_xor_sync(0xffffffffu, tm0, 2));
        tm8 = fmaxf(tm8, __shfl_xor_sync(0xffffffffu, tm8, 1));
        tm8 = fmaxf(tm8, __shfl_xor_sync(0xffffffffu, tm8, 2));

        float nm0 = fmaxf(mx0, tm0), nm8 = fmaxf(mx8, tm8);
        float cr0 = __expf(mx0 - nm0), cr8 = __expf(mx8 - nm8);
        mx0 = nm0; mx8 = nm8;

        float rs0 = 0.f, rs8 = 0.f;
#pragma unroll
        for (int j = 0; j < 8; j++) {
            float p0 = __expf(sc[j][0] - nm0);
            float p1 = __expf(sc[j][1] - nm0);
            float p2 = __expf(sc[j][2] - nm8);
            float p3 = __expf(sc[j][3] - nm8);
            rs0 += p0 + p1; rs8 += p2 + p3;
            int col = j * 8 + cq * 2;
            Ps[(m0 + r) * PSS + col]     = f2tf32(p0);
            Ps[(m0 + r) * PSS + col + 1] = f2tf32(p1);
            Ps[(m0 + r + 8) * PSS + col]     = f2tf32(p2);
            Ps[(m0 + r + 8) * PSS + col + 1] = f2tf32(p3);
        }
        rs0 += __shfl_xor_sync(0xffffffffu, rs0, 1);
        rs0 += __shfl_xor_sync(0xffffffffu, rs0, 2);
        rs8 += __shfl_xor_sync(0xffffffffu, rs8, 1);
        rs8 += __shfl_xor_sync(0xffffffffu, rs8, 2);
        l0 = l0 * cr0 + rs0;
        l8 = l8 * cr8 + rs8;

#pragma unroll
        for (int j = 0; j < 16; j++) {
            oa[j][0] *= cr0; oa[j][1] *= cr0;
            oa[j][2] *= cr8; oa[j][3] *= cr8;
        }
        __syncwarp();

#pragma unroll
        for (int kk8 = 0; kk8 < 8; kk8++) {
            int kk = kk8 * 8;
            unsigned a[4];
            int abase = (m0 + r) * PSS + kk + cq;
            a[0] = Ps[abase];
            a[1] = Ps[abase + 8 * PSS];
            a[2] = Ps[abase + 4];
            a[3] = Ps[abase + 8 * PSS + 4];
#pragma unroll
            for (int j = 0; j < 16; j++) {
                unsigned bfr[2];
                bfr[0] = Vs[(kk + cq) * VSS + j * 8 + r];
                bfr[1] = Vs[(kk + cq + 4) * VSS + j * 8 + r];
                mma_tf32(oa[j], a, bfr);
            }
        }
    }

    float inv0 = 1.f / l0, inv8 = 1.f / l8;
    int row0g = qt * AQ + m0 + r;
    int row8g = row0g + 8;
#pragma unroll
    for (int j = 0; j < 16; j++) {
        int col = j * 8 + cq * 2;
        __half2 h0 = __floats2half2_rn(oa[j][0] * inv0, oa[j][1] * inv0);
        __half2 h1 = __floats2half2_rn(oa[j][2] * inv8, oa[j][3] * inv8);
        *(__half2*)(O + (((size_t)b * S_ + row0g) * NH_ + h) * HD_ + col) = h0;
        *(__half2*)(O + (((size_t)b * S_ + row8g) * NH_ + h) * HD_ + col) = h1;
    }
}

// ---------------- launcher ----------------------------------------------------
extern "C" void kernel_launch(void* const* d_in, const int* in_sizes, int n_in,
                              void* d_out, int out_size)
{
    const float* hs   = (const float*)d_in[0];
    const float* cosb = (const float*)d_in[1];
    const float* sinb = (const float*)d_in[2];
    const float* Wq   = (const float*)d_in[3];
    const float* Wk   = (const float*)d_in[4];
    const float* bk   = (const float*)d_in[5];
    const float* Wv   = (const float*)d_in[6];
    const float* bv   = (const float*)d_in[7];
    const float* Wo   = (const float*)d_in[8];
    float* out = (float*)d_out;

    float *qlin, *kvlin, *q, *k, *v, *bkv;
    __half *hs_h, *wq_h, *wkv_h, *wo_h, *att_h;
    cudaGetSymbolAddress((void**)&qlin,  g_qlin);
    cudaGetSymbolAddress((void**)&kvlin, g_kvlin);
    cudaGetSymbolAddress((void**)&q,     g_q);
    cudaGetSymbolAddress((void**)&k,     g_k);
    cudaGetSymbolAddress((void**)&v,     g_v);
    cudaGetSymbolAddress((void**)&hs_h,  g_hs_h);
    cudaGetSymbolAddress((void**)&wq_h,  g_wq_h);
    cudaGetSymbolAddress((void**)&wkv_h, g_wkv_h);
    cudaGetSymbolAddress((void**)&wo_h,  g_wo_h);
    cudaGetSymbolAddress((void**)&att_h, g_att_h);
    cudaGetSymbolAddress((void**)&bkv,   g_bkv);

    const int M = B_ * S_;           // 4096
    const int NKVD = NKV_ * HD_;     // 1024

    // convert operands to fp16 (+ stack Wk|Wv, concat biases)
    int n4a = (M * H_) / 4;
    int n4b = (NKVD * H_) / 4;
    cvt_f16_kernel<<<n4a / 256, 256>>>((const float4*)hs, (uint2*)hs_h, n4a);
    cvt_f16_kernel<<<n4a / 256, 256>>>((const float4*)Wq, (uint2*)wq_h, n4a);
    cvt_f16_kernel<<<n4b / 256, 256>>>((const float4*)Wk, (uint2*)wkv_h, n4b);
    cvt_f16_kernel<<<n4b / 256, 256>>>((const float4*)Wv,
                                       (uint2*)wkv_h + (size_t)NKVD * H_ / 4, n4b);
    cvt_f16_kernel<<<n4a / 256, 256>>>((const float4*)Wo, (uint2*)wo_h, n4a);
    bias_cat_kernel<<<(2 * NKVD) / 256, 256>>>(bk, bv, bkv);

    // projections (fp16 tensor-core GEMMs, fp32 accumulate)
    cudaFuncSetAttribute(gemm_f16p, cudaFuncAttributeMaxDynamicSharedMemorySize, GEMM_SMEM_H);
    gemm_f16p<<<dim3(H_ / 128, M / 128), 256, GEMM_SMEM_H>>>(hs_h, wq_h, nullptr, qlin, M, H_, H_);
    gemm_f16p<<<dim3((2 * NKVD) / 128, M / 128), 256, GEMM_SMEM_H>>>(hs_h, wkv_h, bkv, kvlin, M, 2 * NKVD, H_);

    // rope + layout
    rope_kernel<<<(B_ * NH_ * S_ * HD_) / 256, 256>>>(qlin, cosb, sinb, q, NH_, H_, 0);
    rope_kernel<<<(B_ * NKV_ * S_ * HD_) / 256, 256>>>(kvlin, cosb, sinb, k, NKV_, 2 * NKVD, 0);
    vtrans_kernel<<<(B_ * NKV_ * S_ * HD_) / 256, 256>>>(kvlin, v, 2 * NKVD, NKVD);

    // attention (tf32 tensor-core) -> fp16 output
    cudaFuncSetAttribute(attn_tc_kernel, cudaFuncAttributeMaxDynamicSharedMemorySize, ATT_SMEM);
    attn_tc_kernel<<<dim3(S_ / AQ, NH_, B_), 256, ATT_SMEM>>>(q, k, v, att_h);

    // output projection
    gemm_f16p<<<dim3(H_ / 128, M / 128), 256, GEMM_SMEM_H>>>(att_h, wo_h, nullptr, out, M, H_, H_);
}

// round 9
// speedup vs baseline: 1.6097x; 1.1521x over previous
#include <cuda_runtime.h>
#include <cuda_fp16.h>
#include <math.h>

#define H_    4096
#define NH_   32
#define NKV_  8
#define HD_   128
#define S_    2048
#define B_    2
#define SCALE_ 0.08838834764831845f   // 128^-0.5

// ---------------- scratch (device globals; no allocations allowed) ----------
__device__ float    g_qlin[(size_t)B_ * S_ * H_];
__device__ float    g_kvlin[(size_t)B_ * S_ * 2 * NKV_ * HD_];   // fused K|V
__device__ __half   g_qh[(size_t)B_ * NH_ * S_ * HD_];           // rope'd Q (scaled), fp16
__device__ __half   g_kh[(size_t)B_ * NKV_ * S_ * HD_];          // rope'd K, fp16
__device__ float    g_v[(size_t)B_ * NKV_ * S_ * HD_];
__device__ __half   g_hs_h[(size_t)B_ * S_ * H_];
__device__ __half   g_wq_h[(size_t)H_ * H_];
__device__ __half   g_wkv_h[(size_t)2 * NKV_ * HD_ * H_];        // stacked Wk|Wv
__device__ __half   g_wo_h[(size_t)H_ * H_];
__device__ __half   g_att_h[(size_t)B_ * S_ * H_];
__device__ float    g_bkv[2 * NKV_ * HD_];                       // bk|bv

// ---------------- helpers ----------------------------------------------------
__device__ __forceinline__ unsigned f2tf32(float f) {
    unsigned r;
    asm("cvt.rna.tf32.f32 %0, %1;" : "=r"(r) : "f"(f));
    return r;
}

__device__ __forceinline__ void mma_tf32(float c[4], const unsigned a[4], const unsigned b[2]) {
    asm volatile(
        "mma.sync.aligned.m16n8k8.row.col.f32.tf32.tf32.f32 "
        "{%0,%1,%2,%3}, {%4,%5,%6,%7}, {%8,%9}, {%0,%1,%2,%3};\n"
        : "+f"(c[0]), "+f"(c[1]), "+f"(c[2]), "+f"(c[3])
        : "r"(a[0]), "r"(a[1]), "r"(a[2]), "r"(a[3]), "r"(b[0]), "r"(b[1]));
}

__device__ __forceinline__ void mma_f16(float c[4], const unsigned a[4], const unsigned b[2]) {
    asm volatile(
        "mma.sync.aligned.m16n8k16.row.col.f32.f16.f16.f32 "
        "{%0,%1,%2,%3}, {%4,%5,%6,%7}, {%8,%9}, {%0,%1,%2,%3};\n"
        : "+f"(c[0]), "+f"(c[1]), "+f"(c[2]), "+f"(c[3])
        : "r"(a[0]), "r"(a[1]), "r"(a[2]), "r"(a[3]), "r"(b[0]), "r"(b[1]));
}

__device__ __forceinline__ unsigned smem_u32(const void* p) {
    return (unsigned)__cvta_generic_to_shared(p);
}

// ---------------- convert fp32 -> fp16 ---------------------------------------
__global__ __launch_bounds__(256) void cvt_f16_kernel(
    const float4* __restrict__ in, uint2* __restrict__ out, int n4)
{
    int i = blockIdx.x * blockDim.x + threadIdx.x;
    if (i < n4) {
        float4 v = in[i];
        __half2 h0 = __floats2half2_rn(v.x, v.y);
        __half2 h1 = __floats2half2_rn(v.z, v.w);
        uint2 u;
        u.x = *(unsigned*)&h0;
        u.y = *(unsigned*)&h1;
        out[i] = u;
    }
}

__global__ void bias_cat_kernel(const float* __restrict__ a,
                                const float* __restrict__ b,
                                float* __restrict__ o)
{
    int i = blockIdx.x * blockDim.x + threadIdx.x;
    int n = NKV_ * HD_;
    if (i < n) o[i] = a[i];
    else if (i < 2 * n) o[i] = b[i - n];
}

// ---------------- pipelined fp16 GEMM (R5 config): C = A @ B^T (+bias) ------
// 128x128x64 tiles, cp.async 2-stage, 8 warps (2m x 4n), warp 64x32, 2 CTA/SM.
#define GSTH 36                       // smem row stride (32-bit words); 36%32==4
#define GSTAGE_H (128 * GSTH)         // words per operand per stage
#define GEMM_SMEM_H (2 * 2 * GSTAGE_H * 4)   // 73728 bytes

__global__ __launch_bounds__(256, 2) void gemm_f16p(
    const __half* __restrict__ A, const __half* __restrict__ Bm,
    const float* __restrict__ bias, float* __restrict__ C,
    int M, int N, int K)
{
    extern __shared__ unsigned sh[];

    int tid = threadIdx.x;
    int warp = tid >> 5, lane = tid & 31;
    int r = lane >> 2, cq = lane & 3;
    int wm = (warp >> 2) * 64, wn = (warp & 3) * 32;
    int bm = blockIdx.y * 128, bn = blockIdx.x * 128;
    int Kw = K >> 1;                  // K in 32-bit words (half2)

    float acc[4][4][4];
#pragma unroll
    for (int mi = 0; mi < 4; mi++)
#pragma unroll
        for (int ni = 0; ni < 4; ni++)
#pragma unroll
            for (int t = 0; t < 4; t++) acc[mi][ni][t] = 0.f;

    int qrow = tid >> 3, qq = (tid & 7) << 2;

    const unsigned* Ab = (const unsigned*)A + (size_t)bm * Kw;
    const unsigned* Bb = (const unsigned*)Bm + (size_t)bn * Kw;

    auto load_stage = [&](int kt, int s) {
        unsigned* As = sh + s * 2 * GSTAGE_H;
        unsigned* Bs = As + GSTAGE_H;
        int k0 = kt << 5;
#pragma unroll
        for (int i = 0; i < 4; i++) {
            int row = qrow + i * 32;
            unsigned da = smem_u32(&As[row * GSTH + qq]);
            const unsigned* sa = Ab + (size_t)row * Kw + k0 + qq;
            asm volatile("cp.async.cg.shared.global [%0], [%1], 16;\n" :: "r"(da), "l"(sa));
            unsigned db = smem_u32(&Bs[row * GSTH + qq]);
            const unsigned* sb = Bb + (size_t)row * Kw + k0 + qq;
            asm volatile("cp.async.cg.shared.global [%0], [%1], 16;\n" :: "r"(db), "l"(sb));
        }
        asm volatile("cp.async.commit_group;\n");
    };

    int nt = K >> 6;
    load_stage(0, 0);

    for (int kt = 0; kt < nt; kt++) {
        if (kt + 1 < nt) {
            load_stage(kt + 1, (kt + 1) & 1);
            asm volatile("cp.async.wait_group 1;\n");
        } else {
            asm volatile("cp.async.wait_group 0;\n");
        }
        __syncthreads();

        unsigned* As = sh + (kt & 1) * 2 * GSTAGE_H;
        unsigned* Bs = As + GSTAGE_H;
#pragma unroll
        for (int k = 0; k < 32; k += 8) {     // 4 k16 steps
            unsigned a[4][4], b[4][2];
#pragma unroll
            for (int mi = 0; mi < 4; mi++) {
                int base = (wm + mi * 16 + r) * GSTH + k + cq;
                a[mi][0] = As[base];
                a[mi][1] = As[base + 8 * GSTH];
                a[mi][2] = As[base + 4];
                a[mi][3] = As[base + 8 * GSTH + 4];
            }
#pragma unroll
            for (int ni = 0; ni < 4; ni++) {
                int base = (wn + ni * 8 + r) * GSTH + k + cq;
                b[ni][0] = Bs[base];
                b[ni][1] = Bs[base + 4];
            }
#pragma unroll
            for (int mi = 0; mi < 4; mi++)
#pragma unroll
                for (int ni = 0; ni < 4; ni++)
                    mma_f16(acc[mi][ni], a[mi], b[ni]);
        }
        __syncthreads();
    }

#pragma unroll
    for (int mi = 0; mi < 4; mi++) {
#pragma unroll
        for (int ni = 0; ni < 4; ni++) {
            int row = bm + wm + mi * 16 + r;
            int col = bn + wn + ni * 8 + cq * 2;
            float b0 = 0.f, b1 = 0.f;
            if (bias) { b0 = bias[col]; b1 = bias[col + 1]; }
            float2 v0, v1;
            v0.x = acc[mi][ni][0] + b0; v0.y = acc[mi][ni][1] + b1;
            v1.x = acc[mi][ni][2] + b0; v1.y = acc[mi][ni][3] + b1;
            *(float2*)(C + (size_t)row * N + col) = v0;
            *(float2*)(C + (size_t)(row + 8) * N + col) = v1;
        }
    }
}

// ---------------- RoPE + head transpose -> fp16 ------------------------------
// reads [B,S,rowstride] at coloff, writes [B,nh,S,HD] as __half, scaled
__global__ void rope_kernel(const float* __restrict__ X, const float* __restrict__ cs,
                            const float* __restrict__ sn, __half* __restrict__ out,
                            int nheads, int rowstride, int coloff, float scale)
{
    int idx = blockIdx.x * blockDim.x + threadIdx.x;
    int d  = idx & (HD_ - 1);
    int s  = (idx >> 7) & (S_ - 1);
    int bh = idx >> 18;
    int h  = bh % nheads;
    int b  = bh / nheads;
    const float* xp = X + (size_t)(b * S_ + s) * rowstride + coloff + h * HD_;
    int dd = d & 63;
    float c = cs[s * 64 + dd], si = sn[s * 64 + dd];
    float x1 = xp[2 * dd], x2 = xp[2 * dd + 1];
    float v = (d < 64) ? (x1 * c - x2 * si) : (x1 * si + x2 * c);
    out[idx] = __float2half(v * scale);
}

__global__ void vtrans_kernel(const float* __restrict__ X, float* __restrict__ out,
                              int rowstride, int coloff)
{
    int idx = blockIdx.x * blockDim.x + threadIdx.x;
    int d  = idx & (HD_ - 1);
    int s  = (idx >> 7) & (S_ - 1);
    int bh = idx >> 18;
    int h  = bh % NKV_;
    int b  = bh / NKV_;
    out[idx] = X[(size_t)(b * S_ + s) * rowstride + coloff + h * HD_ + d];
}

// ---------------- Tensor-core flash attention (fp16 QK, tf32 PV) -------------
#define AQ  128
#define AKV 64
#define QKSW 68    // Q/K smem row stride in words (64 data + 4 pad); 68%32==4
#define VSS 136
#define PSS 68

#define QS_OFF 0
#define KS_OFF (AQ * QKSW)                   // 8704
#define VS_OFF (KS_OFF + AKV * QKSW)         // 13056
#define PS_OFF (VS_OFF + AKV * VSS)          // 21760
#define ATT_WORDS (PS_OFF + AQ * PSS)        // 30464
#define ATT_SMEM (ATT_WORDS * 4)             // 121856 bytes

__global__ __launch_bounds__(256) void attn_tc_kernel(
    const __half* __restrict__ Q,  // [B,NH,S,HD] fp16, pre-scaled
    const __half* __restrict__ K,  // [B,NKV,S,HD] fp16
    const float* __restrict__ V,   // [B,NKV,S,HD] fp32
    __half* __restrict__ O)        // [B,S,NH,HD] fp16
{
    extern __shared__ unsigned smw[];
    unsigned* Qs = smw + QS_OFF;
    unsigned* Ks = smw + KS_OFF;
    unsigned* Vs = smw + VS_OFF;
    unsigned* Ps = smw + PS_OFF;

    int tid = threadIdx.x;
    int warp = tid >> 5, lane = tid & 31;
    int r = lane >> 2, cq = lane & 3;
    int m0 = warp * 16;

    int qt = blockIdx.x, h = blockIdx.y, b = blockIdx.z;
    int kvh = h >> 2;
    const __half* Qp = Q + (((size_t)b * NH_ + h) * S_ + qt * AQ) * HD_;
    const __half* Kp = K + ((size_t)b * NKV_ + kvh) * S_ * HD_;
    const float*  Vp = V + ((size_t)b * NKV_ + kvh) * S_ * HD_;

    // ---- load Q tile: 128 rows x 64 words = 2048 uint4, 8/thread ----
#pragma unroll
    for (int i = 0; i < 8; i++) {
        int fidx = tid + i * 256;
        int rr = fidx >> 4, w4 = (fidx & 15) << 2;    // word col
        uint4 u = *((const uint4*)(Qp + (size_t)rr * HD_) + (fidx & 15));
        *(uint4*)&Qs[rr * QKSW + w4] = u;
    }

    float mx0 = -1e30f, mx8 = -1e30f, l0 = 0.f, l8 = 0.f;
    float oa[16][4];
#pragma unroll
    for (int j = 0; j < 16; j++)
#pragma unroll
        for (int t = 0; t < 4; t++) oa[j][t] = 0.f;

    for (int kt = 0; kt < S_ / AKV; kt++) {
        __syncthreads();
        const __half* Kt = Kp + (size_t)kt * AKV * HD_;
        const float*  Vt = Vp + (size_t)kt * AKV * HD_;
        // K tile: 64 rows x 64 words = 1024 uint4, 4/thread
#pragma unroll
        for (int i = 0; i < 4; i++) {
            int fidx = tid + i * 256;
            int rr = fidx >> 4, w4 = (fidx & 15) << 2;
            uint4 u = *((const uint4*)(Kt + (size_t)rr * HD_) + (fidx & 15));
            *(uint4*)&Ks[rr * QKSW + w4] = u;
        }
        // V tile: 64 x 128 floats -> tf32, 2048 float4, 8/thread
#pragma unroll
        for (int i = 0; i < 8; i++) {
            int fidx = tid + i * 256;
            int rr = fidx >> 5, c4 = (fidx & 31) << 2;
            float4 vv4 = *(const float4*)(Vt + (size_t)rr * HD_ + c4);
            uint4 vu;
            vu.x = f2tf32(vv4.x); vu.y = f2tf32(vv4.y);
            vu.z = f2tf32(vv4.z); vu.w = f2tf32(vv4.w);
            *(uint4*)&Vs[rr * VSS + c4] = vu;
        }
        __syncthreads();

        // ---- scores (fp16): warp computes m16 x 64 over HD=128 = 8 k16 steps
        float sc[8][4];
#pragma unroll
        for (int j = 0; j < 8; j++)
#pragma unroll
            for (int t = 0; t < 4; t++) sc[j][t] = 0.f;

#pragma unroll
        for (int k8 = 0; k8 < 8; k8++) {
            int k = k8 * 8;                   // word offset (16 halves)
            unsigned a[4];
            int abase = (m0 + r) * QKSW + k + cq;
            a[0] = Qs[abase];
            a[1] = Qs[abase + 8 * QKSW];
            a[2] = Qs[abase + 4];
            a[3] = Qs[abase + 8 * QKSW + 4];
#pragma unroll
            for (int j = 0; j < 8; j++) {
                unsigned bfr[2];
                int bbase = (j * 8 + r) * QKSW + k + cq;
                bfr[0] = Ks[bbase];
                bfr[1] = Ks[bbase + 4];
                mma_f16(sc[j], a, bfr);
            }
        }

        // ---- online softmax (rows r and r+8, in-warp) ----
        float tm0 = -1e30f, tm8 = -1e30f;
#pragma unroll
        for (int j = 0; j < 8; j++) {
            tm0 = fmaxf(tm0, fmaxf(sc[j][0], sc[j][1]));
            tm8 = fmaxf(tm8, fmaxf(sc[j][2], sc[j][3]));
        }
        tm0 = fmaxf(tm0, __shfl_xor_sync(0xffffffffu, tm0, 1));
        tm0 = fmaxf(tm0, __shfl_xor_sync(0xffffffffu, tm0, 2));
        tm8 = fmaxf(tm8, __shfl_xor_sync(0xffffffffu, tm8, 1));
        tm8 = fmaxf(tm8, __shfl_xor_sync(0xffffffffu, tm8, 2));

        float nm0 = fmaxf(mx0, tm0), nm8 = fmaxf(mx8, tm8);
        float cr0 = __expf(mx0 - nm0), cr8 = __expf(mx8 - nm8);
        mx0 = nm0; mx8 = nm8;

        float rs0 = 0.f, rs8 = 0.f;
#pragma unroll
        for (int j = 0; j < 8; j++) {
            float p0 = __expf(sc[j][0] - nm0);
            float p1 = __expf(sc[j][1] - nm0);
            float p2 = __expf(sc[j][2] - nm8);
            float p3 = __expf(sc[j][3] - nm8);
            rs0 += p0 + p1; rs8 += p2 + p3;
            int col = j * 8 + cq * 2;
            Ps[(m0 + r) * PSS + col]     = f2tf32(p0);
            Ps[(m0 + r) * PSS + col + 1] = f2tf32(p1);
            Ps[(m0 + r + 8) * PSS + col]     = f2tf32(p2);
            Ps[(m0 + r + 8) * PSS + col + 1] = f2tf32(p3);
        }
        rs0 += __shfl_xor_sync(0xffffffffu, rs0, 1);
        rs0 += __shfl_xor_sync(0xffffffffu, rs0, 2);
        rs8 += __shfl_xor_sync(0xffffffffu, rs8, 1);
        rs8 += __shfl_xor_sync(0xffffffffu, rs8, 2);
        l0 = l0 * cr0 + rs0;
        l8 = l8 * cr8 + rs8;

#pragma unroll
        for (int j = 0; j < 16; j++) {
            oa[j][0] *= cr0; oa[j][1] *= cr0;
            oa[j][2] *= cr8; oa[j][3] *= cr8;
        }
        __syncwarp();

        // ---- PV (tf32): O(m16 x HD) += P(m16 x 64) @ V(64 x HD) ----
#pragma unroll
        for (int kk8 = 0; kk8 < 8; kk8++) {
            int kk = kk8 * 8;
            unsigned a[4];
            int abase = (m0 + r) * PSS + kk + cq;
            a[0] = Ps[abase];
            a[1] = Ps[abase + 8 * PSS];
            a[2] = Ps[abase + 4];
            a[3] = Ps[abase + 8 * PSS + 4];
#pragma unroll
            for (int j = 0; j < 16; j++) {
                unsigned bfr[2];
                bfr[0] = Vs[(kk + cq) * VSS + j * 8 + r];
                bfr[1] = Vs[(kk + cq + 4) * VSS + j * 8 + r];
                mma_tf32(oa[j], a, bfr);
            }
        }
    }

    float inv0 = 1.f / l0, inv8 = 1.f / l8;
    int row0g = qt * AQ + m0 + r;
    int row8g = row0g + 8;
#pragma unroll
    for (int j = 0; j < 16; j++) {
        int col = j * 8 + cq * 2;
        __half2 h0 = __floats2half2_rn(oa[j][0] * inv0, oa[j][1] * inv0);
        __half2 h1 = __floats2half2_rn(oa[j][2] * inv8, oa[j][3] * inv8);
        *(__half2*)(O + (((size_t)b * S_ + row0g) * NH_ + h) * HD_ + col) = h0;
        *(__half2*)(O + (((size_t)b * S_ + row8g) * NH_ + h) * HD_ + col) = h1;
    }
}

// ---------------- launcher ----------------------------------------------------
extern "C" void kernel_launch(void* const* d_in, const int* in_sizes, int n_in,
                              void* d_out, int out_size)
{
    const float* hs   = (const float*)d_in[0];
    const float* cosb = (const float*)d_in[1];
    const float* sinb = (const float*)d_in[2];
    const float* Wq   = (const float*)d_in[3];
    const float* Wk   = (const float*)d_in[4];
    const float* bk   = (const float*)d_in[5];
    const float* Wv   = (const float*)d_in[6];
    const float* bv   = (const float*)d_in[7];
    const float* Wo   = (const float*)d_in[8];
    float* out = (float*)d_out;

    float *qlin, *kvlin, *v, *bkv;
    __half *qh, *kh, *hs_h, *wq_h, *wkv_h, *wo_h, *att_h;
    cudaGetSymbolAddress((void**)&qlin,  g_qlin);
    cudaGetSymbolAddress((void**)&kvlin, g_kvlin);
    cudaGetSymbolAddress((void**)&qh,    g_qh);
    cudaGetSymbolAddress((void**)&kh,    g_kh);
    cudaGetSymbolAddress((void**)&v,     g_v);
    cudaGetSymbolAddress((void**)&hs_h,  g_hs_h);
    cudaGetSymbolAddress((void**)&wq_h,  g_wq_h);
    cudaGetSymbolAddress((void**)&wkv_h, g_wkv_h);
    cudaGetSymbolAddress((void**)&wo_h,  g_wo_h);
    cudaGetSymbolAddress((void**)&att_h, g_att_h);
    cudaGetSymbolAddress((void**)&bkv,   g_bkv);

    const int M = B_ * S_;           // 4096
    const int NKVD = NKV_ * HD_;     // 1024

    // convert operands to fp16 (+ stack Wk|Wv, concat biases)
    int n4a = (M * H_) / 4;
    int n4b = (NKVD * H_) / 4;
    cvt_f16_kernel<<<n4a / 256, 256>>>((const float4*)hs, (uint2*)hs_h, n4a);
    cvt_f16_kernel<<<n4a / 256, 256>>>((const float4*)Wq, (uint2*)wq_h, n4a);
    cvt_f16_kernel<<<n4b / 256, 256>>>((const float4*)Wk, (uint2*)wkv_h, n4b);
    cvt_f16_kernel<<<n4b / 256, 256>>>((const float4*)Wv,
                                       (uint2*)wkv_h + (size_t)NKVD * H_ / 4, n4b);
    cvt_f16_kernel<<<n4a / 256, 256>>>((const float4*)Wo, (uint2*)wo_h, n4a);
    bias_cat_kernel<<<(2 * NKVD) / 256, 256>>>(bk, bv, bkv);

    // projections (fp16 tensor-core GEMMs, fp32 accumulate)
    cudaFuncSetAttribute(gemm_f16p, cudaFuncAttributeMaxDynamicSharedMemorySize, GEMM_SMEM_H);
    gemm_f16p<<<dim3(H_ / 128, M / 128), 256, GEMM_SMEM_H>>>(hs_h, wq_h, nullptr, qlin, M, H_, H_);
    gemm_f16p<<<dim3((2 * NKVD) / 128, M / 128), 256, GEMM_SMEM_H>>>(hs_h, wkv_h, bkv, kvlin, M, 2 * NKVD, H_);

    // rope + layout (Q pre-scaled, fp16 out)
    rope_kernel<<<(B_ * NH_ * S_ * HD_) / 256, 256>>>(qlin, cosb, sinb, qh, NH_, H_, 0, SCALE_);
    rope_kernel<<<(B_ * NKV_ * S_ * HD_) / 256, 256>>>(kvlin, cosb, sinb, kh, NKV_, 2 * NKVD, 0, 1.0f);
    vtrans_kernel<<<(B_ * NKV_ * S_ * HD_) / 256, 256>>>(kvlin, v, 2 * NKVD, NKVD);

    // attention (fp16 QK, tf32 PV) -> fp16 output
    cudaFuncSetAttribute(attn_tc_kernel, cudaFuncAttributeMaxDynamicSharedMemorySize, ATT_SMEM);
    attn_tc_kernel<<<dim3(S_ / AQ, NH_, B_), 256, ATT_SMEM>>>(qh, kh, v, att_h);

    // output projection
    gemm_f16p<<<dim3(H_ / 128, M / 128), 256, GEMM_SMEM_H>>>(att_h, wo_h, nullptr, out, M, H_, H_);
}

// round 11
// speedup vs baseline: 1.6286x; 1.0117x over previous
#include <cuda_runtime.h>
#include <cuda_fp16.h>
#include <math.h>

#define H_    4096
#define NH_   32
#define NKV_  8
#define HD_   128
#define S_    2048
#define B_    2
#define SCALE_ 0.08838834764831845f   // 128^-0.5

// ---------------- scratch (device globals; no allocations allowed) ----------
__device__ __half   g_qh[(size_t)B_ * NH_ * S_ * HD_];           // rope'd Q (scaled), fp16
__device__ __half   g_kh[(size_t)B_ * NKV_ * S_ * HD_];          // rope'd K, fp16
__device__ float    g_v[(size_t)B_ * NKV_ * S_ * HD_];           // V transposed, fp32
__device__ __half   g_hs_h[(size_t)B_ * S_ * H_];
__device__ __half   g_wq_h[(size_t)H_ * H_];
__device__ __half   g_wkv_h[(size_t)2 * NKV_ * HD_ * H_];        // stacked Wk|Wv
__device__ __half   g_wo_h[(size_t)H_ * H_];
__device__ __half   g_att_h[(size_t)B_ * S_ * H_];
__device__ float    g_bkv[2 * NKV_ * HD_];                       // bk|bv

// ---------------- helpers ----------------------------------------------------
__device__ __forceinline__ unsigned f2tf32(float f) {
    unsigned r;
    asm("cvt.rna.tf32.f32 %0, %1;" : "=r"(r) : "f"(f));
    return r;
}

__device__ __forceinline__ void mma_tf32(float c[4], const unsigned a[4], const unsigned b[2]) {
    asm volatile(
        "mma.sync.aligned.m16n8k8.row.col.f32.tf32.tf32.f32 "
        "{%0,%1,%2,%3}, {%4,%5,%6,%7}, {%8,%9}, {%0,%1,%2,%3};\n"
        : "+f"(c[0]), "+f"(c[1]), "+f"(c[2]), "+f"(c[3])
        : "r"(a[0]), "r"(a[1]), "r"(a[2]), "r"(a[3]), "r"(b[0]), "r"(b[1]));
}

__device__ __forceinline__ void mma_f16(float c[4], const unsigned a[4], const unsigned b[2]) {
    asm volatile(
        "mma.sync.aligned.m16n8k16.row.col.f32.f16.f16.f32 "
        "{%0,%1,%2,%3}, {%4,%5,%6,%7}, {%8,%9}, {%0,%1,%2,%3};\n"
        : "+f"(c[0]), "+f"(c[1]), "+f"(c[2]), "+f"(c[3])
        : "r"(a[0]), "r"(a[1]), "r"(a[2]), "r"(a[3]), "r"(b[0]), "r"(b[1]));
}

__device__ __forceinline__ unsigned smem_u32(const void* p) {
    return (unsigned)__cvta_generic_to_shared(p);
}

// ---------------- convert fp32 -> fp16 ---------------------------------------
__global__ __launch_bounds__(256) void cvt_f16_kernel(
    const float4* __restrict__ in, uint2* __restrict__ out, int n4)
{
    int i = blockIdx.x * blockDim.x + threadIdx.x;
    if (i < n4) {
        float4 v = in[i];
        __half2 h0 = __floats2half2_rn(v.x, v.y);
        __half2 h1 = __floats2half2_rn(v.z, v.w);
        uint2 u;
        u.x = *(unsigned*)&h0;
        u.y = *(unsigned*)&h1;
        out[i] = u;
    }
}

__global__ void bias_cat_kernel(const float* __restrict__ a,
                                const float* __restrict__ b,
                                float* __restrict__ o)
{
    int i = blockIdx.x * blockDim.x + threadIdx.x;
    int n = NKV_ * HD_;
    if (i < n) o[i] = a[i];
    else if (i < 2 * n) o[i] = b[i - n];
}

// ---------------- pipelined fp16 GEMM (R5 mainloop): C = A @ B^T (+bias) ----
// 128x128x64 tiles, cp.async 2-stage, 8 warps (2m x 4n), warp 64x32, 2 CTA/SM.
// Epilogue modes: 0 = fp32 C; 1 = RoPE+scale -> OH fp16 [B,NH,S,HD];
//                 2 = col<1024: RoPE -> OH fp16 [B,NKV,S,HD]; col>=1024: V -> OV fp32
#define GSTH 36                       // smem row stride (32-bit words); 36%32==4
#define GSTAGE_H (128 * GSTH)         // words per operand per stage
#define GEMM_SMEM_H (2 * 2 * GSTAGE_H * 4)   // 73728 bytes

__global__ __launch_bounds__(256, 2) void gemm_f16p(
    const __half* __restrict__ A, const __half* __restrict__ Bm,
    const float* __restrict__ bias, float* __restrict__ C,
    __half* __restrict__ OH, float* __restrict__ OV,
    const float* __restrict__ cosb, const float* __restrict__ sinb,
    int M, int N, int K, int mode)
{
    extern __shared__ unsigned sh[];

    int tid = threadIdx.x;
    int warp = tid >> 5, lane = tid & 31;
    int r = lane >> 2, cq = lane & 3;
    int wm = (warp >> 2) * 64, wn = (warp & 3) * 32;
    int bm = blockIdx.y * 128, bn = blockIdx.x * 128;
    int Kw = K >> 1;                  // K in 32-bit words (half2)

    float acc[4][4][4];
#pragma unroll
    for (int mi = 0; mi < 4; mi++)
#pragma unroll
        for (int ni = 0; ni < 4; ni++)
#pragma unroll
            for (int t = 0; t < 4; t++) acc[mi][ni][t] = 0.f;

    int qrow = tid >> 3, qq = (tid & 7) << 2;

    const unsigned* Ab = (const unsigned*)A + (size_t)bm * Kw;
    const unsigned* Bb = (const unsigned*)Bm + (size_t)bn * Kw;

    auto load_stage = [&](int kt, int s) {
        unsigned* As = sh + s * 2 * GSTAGE_H;
        unsigned* Bs = As + GSTAGE_H;
        int k0 = kt << 5;
#pragma unroll
        for (int i = 0; i < 4; i++) {
            int row = qrow + i * 32;
            unsigned da = smem_u32(&As[row * GSTH + qq]);
            const unsigned* sa = Ab + (size_t)row * Kw + k0 + qq;
            asm volatile("cp.async.cg.shared.global [%0], [%1], 16;\n" :: "r"(da), "l"(sa));
            unsigned db = smem_u32(&Bs[row * GSTH + qq]);
            const unsigned* sb = Bb + (size_t)row * Kw + k0 + qq;
            asm volatile("cp.async.cg.shared.global [%0], [%1], 16;\n" :: "r"(db), "l"(sb));
        }
        asm volatile("cp.async.commit_group;\n");
    };

    int nt = K >> 6;
    load_stage(0, 0);

    for (int kt = 0; kt < nt; kt++) {
        if (kt + 1 < nt) {
            load_stage(kt + 1, (kt + 1) & 1);
            asm volatile("cp.async.wait_group 1;\n");
        } else {
            asm volatile("cp.async.wait_group 0;\n");
        }
        __syncthreads();

        unsigned* As = sh + (kt & 1) * 2 * GSTAGE_H;
        unsigned* Bs = As + GSTAGE_H;
#pragma unroll
        for (int k = 0; k < 32; k += 8) {     // 4 k16 steps
            unsigned a[4][4], b[4][2];
#pragma unroll
            for (int mi = 0; mi < 4; mi++) {
                int base = (wm + mi * 16 + r) * GSTH + k + cq;
                a[mi][0] = As[base];
                a[mi][1] = As[base + 8 * GSTH];
                a[mi][2] = As[base + 4];
                a[mi][3] = As[base + 8 * GSTH + 4];
            }
#pragma unroll
            for (int ni = 0; ni < 4; ni++) {
                int base = (wn + ni * 8 + r) * GSTH + k + cq;
                b[ni][0] = Bs[base];
                b[ni][1] = Bs[base + 4];
            }
#pragma unroll
            for (int mi = 0; mi < 4; mi++)
#pragma unroll
                for (int ni = 0; ni < 4; ni++)
                    mma_f16(acc[mi][ni], a[mi], b[ni]);
        }
        __syncthreads();
    }

    // ---------------- epilogue ----------------
#pragma unroll
    for (int mi = 0; mi < 4; mi++) {
#pragma unroll
        for (int ni = 0; ni < 4; ni++) {
            int col = bn + wn + ni * 8 + cq * 2;
            float b0 = 0.f, b1 = 0.f;
            if (bias) { b0 = bias[col]; b1 = bias[col + 1]; }
            if (mode == 0) {
                int row = bm + wm + mi * 16 + r;
                float2 v0, v1;
                v0.x = acc[mi][ni][0] + b0; v0.y = acc[mi][ni][1] + b1;
                v1.x = acc[mi][ni][2] + b0; v1.y = acc[mi][ni][3] + b1;
                *(float2*)(C + (size_t)row * N + col) = v0;
                *(float2*)(C + (size_t)(row + 8) * N + col) = v1;
            } else {
#pragma unroll
                for (int t = 0; t < 2; t++) {
                    int rowX = bm + wm + mi * 16 + r + t * 8;
                    float v0 = acc[mi][ni][t * 2]     + b0;
                    float v1 = acc[mi][ni][t * 2 + 1] + b1;
                    int bb = rowX >> 11, s = rowX & (S_ - 1);
                    if (mode == 1 || col < NKV_ * HD_) {
                        // RoPE pair (v0 = x[2dd], v1 = x[2dd+1])
                        int hh = col >> 7;
                        int dd = (col & 127) >> 1;
                        float cv = cosb[s * 64 + dd], sv = sinb[s * 64 + dd];
                        float o1 = v0 * cv - v1 * sv;
                        float o2 = v0 * sv + v1 * cv;
                        if (mode == 1) { o1 *= SCALE_; o2 *= SCALE_; }
                        int nh = (mode == 1) ? NH_ : NKV_;
                        __half* op = OH + (((size_t)bb * nh + hh) * S_ + s) * HD_;
                        op[dd]      = __float2half(o1);
                        op[64 + dd] = __float2half(o2);
                    } else {
                        // V half: transposed store [B,NKV,S,HD]
                        int cvv = col - NKV_ * HD_;
                        int hh = cvv >> 7, d = cvv & 127;
                        float2 w; w.x = v0; w.y = v1;
                        *(float2*)(OV + (((size_t)bb * NKV_ + hh) * S_ + s) * HD_ + d) = w;
                    }
                }
            }
        }
    }
}

// ---------------- Tensor-core flash attention (fp16 QK, tf32 PV) -------------
#define AQ  128
#define AKV 64
#define QKSW 68    // Q/K smem row stride in words; 68%32==4
#define VSS 136
#define PSS 68

#define QS_OFF 0
#define KS_OFF (AQ * QKSW)
#define VS_OFF (KS_OFF + AKV * QKSW)
#define PS_OFF (VS_OFF + AKV * VSS)
#define ATT_WORDS (PS_OFF + AQ * PSS)
#define ATT_SMEM (ATT_WORDS * 4)

__global__ __launch_bounds__(256) void attn_tc_kernel(
    const __half* __restrict__ Q,  // [B,NH,S,HD] fp16, pre-scaled
    const __half* __restrict__ K,  // [B,NKV,S,HD] fp16
    const float* __restrict__ V,   // [B,NKV,S,HD] fp32
    __half* __restrict__ O)        // [B,S,NH,HD] fp16
{
    extern __shared__ unsigned smw[];
    unsigned* Qs = smw + QS_OFF;
    unsigned* Ks = smw + KS_OFF;
    unsigned* Vs = smw + VS_OFF;
    unsigned* Ps = smw + PS_OFF;

    int tid = threadIdx.x;
    int warp = tid >> 5, lane = tid & 31;
    int r = lane >> 2, cq = lane & 3;
    int m0 = warp * 16;

    int qt = blockIdx.x, h = blockIdx.y, b = blockIdx.z;
    int kvh = h >> 2;
    const __half* Qp = Q + (((size_t)b * NH_ + h) * S_ + qt * AQ) * HD_;
    const __half* Kp = K + ((size_t)b * NKV_ + kvh) * S_ * HD_;
    const float*  Vp = V + ((size_t)b * NKV_ + kvh) * S_ * HD_;

#pragma unroll
    for (int i = 0; i < 8; i++) {
        int fidx = tid + i * 256;
        int rr = fidx >> 4, w4 = (fidx & 15) << 2;
        uint4 u = *((const uint4*)(Qp + (size_t)rr * HD_) + (fidx & 15));
        *(uint4*)&Qs[rr * QKSW + w4] = u;
    }

    float mx0 = -1e30f, mx8 = -1e30f, l0 = 0.f, l8 = 0.f;
    float oa[16][4];
#pragma unroll
    for (int j = 0; j < 16; j++)
#pragma unroll
        for (int t = 0; t < 4; t++) oa[j][t] = 0.f;

    for (int kt = 0; kt < S_ / AKV; kt++) {
        __syncthreads();
        const __half* Kt = Kp + (size_t)kt * AKV * HD_;
        const float*  Vt = Vp + (size_t)kt * AKV * HD_;
#pragma unroll
        for (int i = 0; i < 4; i++) {
            int fidx = tid + i * 256;
            int rr = fidx >> 4, w4 = (fidx & 15) << 2;
            uint4 u = *((const uint4*)(Kt + (size_t)rr * HD_) + (fidx & 15));
            *(uint4*)&Ks[rr * QKSW + w4] = u;
        }
#pragma unroll
        for (int i = 0; i < 8; i++) {
            int fidx = tid + i * 256;
            int rr = fidx >> 5, c4 = (fidx & 31) << 2;
            float4 vv4 = *(const float4*)(Vt + (size_t)rr * HD_ + c4);
            uint4 vu;
            vu.x = f2tf32(vv4.x); vu.y = f2tf32(vv4.y);
            vu.z = f2tf32(vv4.z); vu.w = f2tf32(vv4.w);
            *(uint4*)&Vs[rr * VSS + c4] = vu;
        }
        __syncthreads();

        float sc[8][4];
#pragma unroll
        for (int j = 0; j < 8; j++)
#pragma unroll
            for (int t = 0; t < 4; t++) sc[j][t] = 0.f;

#pragma unroll
        for (int k8 = 0; k8 < 8; k8++) {
            int k = k8 * 8;
            unsigned a[4];
            int abase = (m0 + r) * QKSW + k + cq;
            a[0] = Qs[abase];
            a[1] = Qs[abase + 8 * QKSW];
            a[2] = Qs[abase + 4];
            a[3] = Qs[abase + 8 * QKSW + 4];
#pragma unroll
            for (int j = 0; j < 8; j++) {
                unsigned bfr[2];
                int bbase = (j * 8 + r) * QKSW + k + cq;
                bfr[0] = Ks[bbase];
                bfr[1] = Ks[bbase + 4];
                mma_f16(sc[j], a, bfr);
            }
        }

        float tm0 = -1e30f, tm8 = -1e30f;
#pragma unroll
        for (int j = 0; j < 8; j++) {
            tm0 = fmaxf(tm0, fmaxf(sc[j][0], sc[j][1]));
            tm8 = fmaxf(tm8, fmaxf(sc[j][2], sc[j][3]));
        }
        tm0 = fmaxf(tm0, __shfl_xor_sync(0xffffffffu, tm0, 1));
        tm0 = fmaxf(tm0, __shfl_xor_sync(0xffffffffu, tm0, 2));
        tm8 = fmaxf(tm8, __shfl_xor_sync(0xffffffffu, tm8, 1));
        tm8 = fmaxf(tm8, __shfl_xor_sync(0xffffffffu, tm8, 2));

        float nm0 = fmaxf(mx0, tm0), nm8 = fmaxf(mx8, tm8);
        float cr0 = __expf(mx0 - nm0), cr8 = __expf(mx8 - nm8);
        mx0 = nm0; mx8 = nm8;

        float rs0 = 0.f, rs8 = 0.f;
#pragma unroll
        for (int j = 0; j < 8; j++) {
            float p0 = __expf(sc[j][0] - nm0);
            float p1 = __expf(sc[j][1] - nm0);
            float p2 = __expf(sc[j][2] - nm8);
            float p3 = __expf(sc[j][3] - nm8);
            rs0 += p0 + p1; rs8 += p2 + p3;
            int col = j * 8 + cq * 2;
            Ps[(m0 + r) * PSS + col]     = f2tf32(p0);
            Ps[(m0 + r) * PSS + col + 1] = f2tf32(p1);
            Ps[(m0 + r + 8) * PSS + col]     = f2tf32(p2);
            Ps[(m0 + r + 8) * PSS + col + 1] = f2tf32(p3);
        }
        rs0 += __shfl_xor_sync(0xffffffffu, rs0, 1);
        rs0 += __shfl_xor_sync(0xffffffffu, rs0, 2);
        rs8 += __shfl_xor_sync(0xffffffffu, rs8, 1);
        rs8 += __shfl_xor_sync(0xffffffffu, rs8, 2);
        l0 = l0 * cr0 + rs0;
        l8 = l8 * cr8 + rs8;

#pragma unroll
        for (int j = 0; j < 16; j++) {
            oa[j][0] *= cr0; oa[j][1] *= cr0;
            oa[j][2] *= cr8; oa[j][3] *= cr8;
        }
        __syncwarp();

#pragma unroll
        for (int kk8 = 0; kk8 < 8; kk8++) {
            int kk = kk8 * 8;
            unsigned a[4];
            int abase = (m0 + r) * PSS + kk + cq;
            a[0] = Ps[abase];
            a[1] = Ps[abase + 8 * PSS];
            a[2] = Ps[abase + 4];
            a[3] = Ps[abase + 8 * PSS + 4];
#pragma unroll
            for (int j = 0; j < 16; j++) {
                unsigned bfr[2];
                bfr[0] = Vs[(kk + cq) * VSS + j * 8 + r];
                bfr[1] = Vs[(kk + cq + 4) * VSS + j * 8 + r];
                mma_tf32(oa[j], a, bfr);
            }
        }
    }

    float inv0 = 1.f / l0, inv8 = 1.f / l8;
    int row0g = qt * AQ + m0 + r;
    int row8g = row0g + 8;
#pragma unroll
    for (int j = 0; j < 16; j++) {
        int col = j * 8 + cq * 2;
        __half2 h0 = __floats2half2_rn(oa[j][0] * inv0, oa[j][1] * inv0);
        __half2 h1 = __floats2half2_rn(oa[j][2] * inv8, oa[j][3] * inv8);
        *(__half2*)(O + (((size_t)b * S_ + row0g) * NH_ + h) * HD_ + col) = h0;
        *(__half2*)(O + (((size_t)b * S_ + row8g) * NH_ + h) * HD_ + col) = h1;
    }
}

// ---------------- launcher ----------------------------------------------------
extern "C" void kernel_launch(void* const* d_in, const int* in_sizes, int n_in,
                              void* d_out, int out_size)
{
    const float* hs   = (const float*)d_in[0];
    const float* cosb = (const float*)d_in[1];
    const float* sinb = (const float*)d_in[2];
    const float* Wq   = (const float*)d_in[3];
    const float* Wk   = (const float*)d_in[4];
    const float* bk   = (const float*)d_in[5];
    const float* Wv   = (const float*)d_in[6];
    const float* bv   = (const float*)d_in[7];
    const float* Wo   = (const float*)d_in[8];
    float* out = (float*)d_out;

    float *v, *bkv;
    __half *qh, *kh, *hs_h, *wq_h, *wkv_h, *wo_h, *att_h;
    cudaGetSymbolAddress((void**)&qh,    g_qh);
    cudaGetSymbolAddress((void**)&kh,    g_kh);
    cudaGetSymbolAddress((void**)&v,     g_v);
    cudaGetSymbolAddress((void**)&hs_h,  g_hs_h);
    cudaGetSymbolAddress((void**)&wq_h,  g_wq_h);
    cudaGetSymbolAddress((void**)&wkv_h, g_wkv_h);
    cudaGetSymbolAddress((void**)&wo_h,  g_wo_h);
    cudaGetSymbolAddress((void**)&att_h, g_att_h);
    cudaGetSymbolAddress((void**)&bkv,   g_bkv);

    const int M = B_ * S_;           // 4096
    const int NKVD = NKV_ * HD_;     // 1024

    // convert operands to fp16 (+ stack Wk|Wv, concat biases)
    int n4a = (M * H_) / 4;
    int n4b = (NKVD * H_) / 4;
    cvt_f16_kernel<<<n4a / 256, 256>>>((const float4*)hs, (uint2*)hs_h, n4a);
    cvt_f16_kernel<<<n4a / 256, 256>>>((const float4*)Wq, (uint2*)wq_h, n4a);
    cvt_f16_kernel<<<n4b / 256, 256>>>((const float4*)Wk, (uint2*)wkv_h, n4b);
    cvt_f16_kernel<<<n4b / 256, 256>>>((const float4*)Wv,
                                       (uint2*)wkv_h + (size_t)NKVD * H_ / 4, n4b);
    cvt_f16_kernel<<<n4a / 256, 256>>>((const float4*)Wo, (uint2*)wo_h, n4a);
    bias_cat_kernel<<<(2 * NKVD) / 256, 256>>>(bk, bv, bkv);

    cudaFuncSetAttribute(gemm_f16p, cudaFuncAttributeMaxDynamicSharedMemorySize, GEMM_SMEM_H);

    // Q projection with fused RoPE+scale -> qh (fp16, [B,NH,S,HD])
    gemm_f16p<<<dim3(H_ / 128, M / 128), 256, GEMM_SMEM_H>>>(
        hs_h, wq_h, nullptr, nullptr, qh, nullptr, cosb, sinb, M, H_, H_, 1);

    // KV projection with fused K-RoPE -> kh and V transpose -> v
    gemm_f16p<<<dim3((2 * NKVD) / 128, M / 128), 256, GEMM_SMEM_H>>>(
        hs_h, wkv_h, bkv, nullptr, kh, v, cosb, sinb, M, 2 * NKVD, H_, 2);

    // attention (fp16 QK, tf32 PV) -> fp16 output
    cudaFuncSetAttribute(attn_tc_kernel, cudaFuncAttributeMaxDynamicSharedMemorySize, ATT_SMEM);
    attn_tc_kernel<<<dim3(S_ / AQ, NH_, B_), 256, ATT_SMEM>>>(qh, kh, v, att_h);

    // output projection (fp32 C)
    gemm_f16p<<<dim3(H_ / 128, M / 128), 256, GEMM_SMEM_H>>>(
        att_h, wo_h, nullptr, out, nullptr, nullptr, nullptr, nullptr, M, H_, H_, 0);
}